// round 17
// baseline (speedup 1.0000x reference)
#include <cuda_runtime.h>
#include <cstdint>
#include <math.h>

#define BB 128
#define TT 512
#define DD 128
#define HH 384
#define GG 1542
#define GPAD 1664
#define HSS 64
#define CK 10
#define GT 24
#define NBLK (GT * 4)
#define KH 384
#define APAD 40

__device__ float g_h[(size_t)TT * BB * HH];
__device__ float g_dist[TT * BB];
__device__ float g_wct[CK * HH * HH];
__device__ float g_xk[(size_t)TT * BB * GPAD];
__device__ unsigned g_cnt2[4];
__device__ unsigned g_gen2[4];
__device__ unsigned g_task;

typedef unsigned long long u64;
__device__ __forceinline__ u64 pk2(float a, float b) {
    u64 r; asm("mov.b64 %0,{%1,%2};" : "=l"(r) : "f"(a), "f"(b)); return r;
}
__device__ __forceinline__ void fma2(u64 &d, u64 a, u64 b) {
    asm("fma.rn.f32x2 %0,%1,%2,%0;" : "+l"(d) : "l"(a), "l"(b));
}
__device__ __forceinline__ float2 up2(u64 v) {
    float2 r; asm("mov.b64 {%0,%1},%2;" : "=f"(r.x), "=f"(r.y) : "l"(v)); return r;
}
__device__ __forceinline__ float ftanh(float x) {
    float y; asm("tanh.approx.f32 %0,%1;" : "=f"(y) : "f"(x)); return y;
}
__device__ __forceinline__ float sgm(float x) { return 0.5f * ftanh(0.5f * x) + 0.5f; }

__device__ __forceinline__ void group_bar(int grp) {
    __syncthreads();
    if (threadIdx.x == 0) {
        unsigned *gp = &g_gen2[grp];
        unsigned old;
        asm volatile("ld.global.u32 %0, [%1];" : "=r"(old) : "l"(gp) : "memory");
        unsigned prev;
        asm volatile("atom.add.acq_rel.gpu.global.u32 %0, [%1], 1;"
                     : "=r"(prev) : "l"(&g_cnt2[grp]) : "memory");
        if (prev == GT - 1) {
            g_cnt2[grp] = 0;
            asm volatile("st.release.gpu.global.u32 [%0], %1;"
                         :: "l"(gp), "r"(old + 1) : "memory");
        } else {
            unsigned v;
            do {
                asm volatile("ld.acquire.gpu.global.u32 %0, [%1];"
                             : "=r"(v) : "l"(gp) : "memory");
            } while (v == old);
        }
    }
    __syncthreads();
}

__device__ __forceinline__ void calc_dis(int t, int b, float *dis) {
    float cs = 0.f, c[CK];
    #pragma unroll
    for (int k = 0; k < CK; k++) {
        int s = t - (CK - 1) + k;
        cs += (s >= 0) ? g_dist[s * BB + b] : 0.f;
        c[k] = cs;
    }
    float mx = c[0];
    #pragma unroll
    for (int k = 1; k < CK; k++) mx = fmaxf(mx, c[k]);
    float sum = 0.f;
    #pragma unroll
    for (int k = 0; k < CK; k++) { c[k] = __expf(c[k] - mx); sum += c[k]; }
    float is = 1.f / sum;
    #pragma unroll
    for (int k = 0; k < CK; k++) dis[k] = c[k] * is;
}

__device__ __forceinline__ void wait_gen_ge(int t) {
    #pragma unroll
    for (int g = 0; g < 4; g++) {
        unsigned v;
        do {
            asm volatile("ld.acquire.gpu.global.u32 %0, [%1];"
                         : "=r"(v) : "l"(&g_gen2[g]) : "memory");
        } while (v < (unsigned)(t + 1));
    }
}

__global__ void init_kernel() {
    int i = blockIdx.x * 256 + threadIdx.x;
    if (i < 4) { g_gen2[i] = 0; g_cnt2[i] = 0; }
    if (i == 0) g_task = 0;
}

__global__ void wct_kernel(const float * __restrict__ Wc) {
    int e = blockIdx.x * 256 + threadIdx.x;
    if (e < CK * HH * HH) {
        int o = e % HH, i = (e / HH) % HH, k = e / (HH * HH);
        g_wct[e] = Wc[((size_t)o * HH + i) * CK + k];
    }
}

// ---------- XK precompute (proven) ----------
#define XK_FFMA(COMP)                                                       \
    {                                                                       \
        ulonglong2 b0v = *(const ulonglong2 *)&Bs[kk][tx * 4];              \
        ulonglong2 b1v = *(const ulonglong2 *)&Bs[kk][tx * 4 + 64];         \
        _Pragma("unroll")                                                   \
        for (int rr = 0; rr < 8; rr++) {                                    \
            float av = a4[rr].COMP;                                         \
            u64 aa = pk2(av, av);                                           \
            fma2(acc[rr][0], aa, b0v.x); fma2(acc[rr][1], aa, b0v.y);       \
            fma2(acc[rr][2], aa, b1v.x); fma2(acc[rr][3], aa, b1v.y);       \
        }                                                                   \
        kk++;                                                               \
    }

__global__ __launch_bounds__(256) void xk_kernel(
    const float * __restrict__ x, const float * __restrict__ Wk,
    const float * __restrict__ bk, const float * __restrict__ Wr,
    const float * __restrict__ br)
{
    int b = blockIdx.x >> 2, t0 = (blockIdx.x & 3) * 128;
    int g0 = blockIdx.y * 128;
    int tid = threadIdx.x, tx = tid & 15, ty = tid >> 4;
    __shared__ __align__(16) float As[128][20];
    __shared__ __align__(16) float Bs[16][128];

    u64 acc[8][4];
    #pragma unroll
    for (int a = 0; a < 8; a++)
        #pragma unroll
        for (int c = 0; c < 4; c++) acc[a][c] = 0ull;

    for (int ch = 0; ch < 8; ch++) {
        int k0 = ch * 16;
        __syncthreads();
        #pragma unroll
        for (int l = 0; l < 8; l++) {
            int e = tid + l * 256;
            As[e >> 4][e & 15] = x[((size_t)b * TT + t0 + (e >> 4)) * DD + k0 + (e & 15)];
            int g = g0 + (e & 127);
            Bs[e >> 7][e & 127] = (g < GG) ? Wk[(size_t)(k0 + (e >> 7)) * GG + g] : 0.f;
        }
        __syncthreads();
        #pragma unroll
        for (int kq = 0; kq < 4; kq++) {
            float4 a4[8];
            #pragma unroll
            for (int rr = 0; rr < 8; rr++)
                a4[rr] = *(const float4 *)&As[ty * 8 + rr][kq * 4];
            int kk = kq * 4;
            XK_FFMA(x) XK_FFMA(y) XK_FFMA(z) XK_FFMA(w)
        }
    }
    #pragma unroll
    for (int rr = 0; rr < 8; rr++) {
        int t = t0 + ty * 8 + rr;
        #pragma unroll
        for (int c = 0; c < 4; c++) {
            float2 v = up2(acc[rr][c]);
            #pragma unroll
            for (int l = 0; l < 2; l++) {
                int g = g0 + (c >> 1) * 64 + tx * 4 + (c & 1) * 2 + l;
                if (g < GG) {
                    float bias = bk[g] + br[g] + Wk[(size_t)DD * GG + g] + Wr[(size_t)HH * GG + g];
                    int gp = (g < 6) ? (1536 + g) : (g - 6);
                    g_xk[((size_t)t * BB + b) * GPAD + gp] = (l ? v.y : v.x) + bias;
                }
            }
        }
    }
}

// ---------- phase-1 body (proven) ----------
__device__ void phase1_body(const float * __restrict__ Wr, float *sm, int blk)
{
    float *Bs   = sm;
    float *Bsm  = Bs + KH * 64;
    float *As   = Bsm + KH * 8;
    float *Msum = As + KH * APAD;
    float *fms  = Msum + 4 * 192;
    float *ims  = fms + 96;

    int tid = threadIdx.x;
    int gt = blk % GT, bt = blk / GT;
    int b0 = bt * 32;

    for (int j = 0; j < (KH * 64) / 512; j++) {
        int e = tid + j * 512;
        int gg = e & 63, k = e >> 6, q = gg >> 4, m = gg & 15;
        Bs[e] = Wr[(size_t)k * GG + 6 + 384 * q + 16 * gt + m];
    }
    for (int e = tid; e < KH * 8; e += 512) {
        int g = e & 7, k = e >> 3;
        Bsm[e] = (g < 6) ? Wr[(size_t)k * GG + g] : 0.f;
    }
    __syncthreads();

    int kc = tid >> 7, r = tid & 127;
    int tx = r & 15, ty = r >> 4;
    int sb = tid >> 4, sj = tid & 15;
    int ub = tid >> 4, um = tid & 15;
    int ui = gt * 16 + um, ul = ui >> 7;
    float creg = 0.f;
    int mid0 = 2 * r, mb = mid0 / 6, mg0 = mid0 % 6;

    for (int t = 0; t < TT; t++) {
        float4 xkp[4];
        if (kc == 0) {
            int gp = 384 * (tx >> 2) + 16 * gt + (tx & 3) * 4;
            #pragma unroll
            for (int a = 0; a < 4; a++)
                xkp[a] = *(const float4 *)&g_xk[((size_t)t * BB + b0 + ty * 4 + a) * GPAD + gp];
        }
        float xkm[6];
        if (tid >= 128 && tid < 160) {
            int b = tid - 128;
            float4 v4 = *(const float4 *)&g_xk[((size_t)t * BB + b0 + b) * GPAD + 1536];
            float2 v2 = *(const float2 *)&g_xk[((size_t)t * BB + b0 + b) * GPAD + 1540];
            xkm[0] = v4.x; xkm[1] = v4.y; xkm[2] = v4.z; xkm[3] = v4.w;
            xkm[4] = v2.x; xkm[5] = v2.y;
        }

        #pragma unroll
        for (int j = 0; j < 6; j++) {
            int k4 = (sj + j * 16) * 4;
            float4 v;
            if (t > 0) v = *(const float4 *)&g_h[((size_t)(t - 1) * BB + b0 + sb) * HH + k4];
            else { v.x = v.y = v.z = v.w = 0.f; }
            As[(k4 + 0) * APAD + sb] = v.x;
            As[(k4 + 1) * APAD + sb] = v.y;
            As[(k4 + 2) * APAD + sb] = v.z;
            As[(k4 + 3) * APAD + sb] = v.w;
        }
        __syncthreads();

        u64 acc[4][2];
        #pragma unroll
        for (int a = 0; a < 4; a++) { acc[a][0] = 0ull; acc[a][1] = 0ull; }
        int kbeg = kc * (KH / 4);
        #pragma unroll 6
        for (int kk = kbeg; kk < kbeg + KH / 4; kk++) {
            float4 av = *(const float4 *)&As[kk * APAD + ty * 4];
            ulonglong2 bv = *(const ulonglong2 *)&Bs[kk * 64 + tx * 4];
            u64 aa;
            aa = pk2(av.x, av.x); fma2(acc[0][0], aa, bv.x); fma2(acc[0][1], aa, bv.y);
            aa = pk2(av.y, av.y); fma2(acc[1][0], aa, bv.x); fma2(acc[1][1], aa, bv.y);
            aa = pk2(av.z, av.z); fma2(acc[2][0], aa, bv.x); fma2(acc[2][1], aa, bv.y);
            aa = pk2(av.w, av.w); fma2(acc[3][0], aa, bv.x); fma2(acc[3][1], aa, bv.y);
        }
        float mp0 = 0.f, mp1 = 0.f;
        if (r < 96) {
            for (int kk = kbeg; kk < kbeg + KH / 4; kk++) {
                float a = As[kk * APAD + mb];
                mp0 += a * Bsm[kk * 8 + mg0];
                mp1 += a * Bsm[kk * 8 + mg0 + 1];
            }
        }
        __syncthreads();

        ulonglong2 *red = (ulonglong2 *)As;
        float *res = (float *)(red + 3 * 512);
        if (kc) {
            #pragma unroll
            for (int a = 0; a < 4; a++) {
                ulonglong2 v; v.x = acc[a][0]; v.y = acc[a][1];
                red[(size_t)(kc - 1) * 512 + a * 128 + r] = v;
            }
        }
        if (r < 96) *(float2 *)&Msum[kc * 192 + mid0] = make_float2(mp0, mp1);
        __syncthreads();

        if (kc == 0) {
            #pragma unroll
            for (int a = 0; a < 4; a++) {
                float2 s0 = up2(acc[a][0]), s1 = up2(acc[a][1]);
                #pragma unroll
                for (int q = 0; q < 3; q++) {
                    ulonglong2 v = red[(size_t)q * 512 + a * 128 + r];
                    float2 o0 = up2(v.x), o1 = up2(v.y);
                    s0.x += o0.x; s0.y += o0.y; s1.x += o1.x; s1.y += o1.y;
                }
                float4 w;
                w.x = s0.x + xkp[a].x; w.y = s0.y + xkp[a].y;
                w.z = s1.x + xkp[a].z; w.w = s1.y + xkp[a].w;
                *(float4 *)&res[(ty * 4 + a) * 64 + tx * 4] = w;
            }
        }
        if (tid >= 128 && tid < 160) {
            int b = tid - 128;
            float pre[6];
            #pragma unroll
            for (int g = 0; g < 6; g++)
                pre[g] = Msum[b * 6 + g] + Msum[192 + b * 6 + g]
                       + Msum[384 + b * 6 + g] + Msum[576 + b * 6 + g] + xkm[g];
            float m = fmaxf(pre[0], fmaxf(pre[1], pre[2]));
            float e0 = __expf(pre[0] - m), e1 = __expf(pre[1] - m), e2 = __expf(pre[2] - m);
            float inv = 1.f / (e0 + e1 + e2);
            float f0 = e0 * inv, f1 = f0 + e1 * inv, f2 = f1 + e2 * inv;
            fms[b * 3 + 0] = f0; fms[b * 3 + 1] = f1; fms[b * 3 + 2] = f2;
            float mi = fmaxf(pre[3], fmaxf(pre[4], pre[5]));
            float q0 = __expf(pre[3] - mi), q1 = __expf(pre[4] - mi), q2 = __expf(pre[5] - mi);
            float iv = 1.f / (q0 + q1 + q2);
            float i2 = q2 * iv, i1 = i2 + q1 * iv, i0 = i1 + q0 * iv;
            ims[b * 3 + 0] = i0; ims[b * 3 + 1] = i1; ims[b * 3 + 2] = i2;
            if (gt == 0) g_dist[t * BB + b0 + b] = 1.f - (f0 + f1 + f2) * (1.f / 3.f);
        }
        __syncthreads();

        {
            float fgv = sgm(res[ub * 64 + um]);
            float igv = sgm(res[ub * 64 + 16 + um]);
            float ogv = sgm(res[ub * 64 + 32 + um]);
            float civ = ftanh(res[ub * 64 + 48 + um]);
            float fm = fms[ub * 3 + ul], im = ims[ub * 3 + ul];
            float ov = fm * im;
            creg = creg * (ov * fgv + fm - ov) + civ * (ov * igv + im - ov);
            g_h[((size_t)t * BB + b0 + ub) * HH + ui] = ogv * ftanh(creg);
        }
        group_bar(bt);
    }
}

// ---------- fused conv+theme block (512 thr, k-fastest chunks) ----------
#define CONV_FFMA(COMP)                                                     \
    {                                                                       \
        ulonglong2 bv = *(const ulonglong2 *)&Bs[kk][tx * 4];               \
        _Pragma("unroll")                                                   \
        for (int rr = 0; rr < 8; rr++) {                                    \
            float av = a4[rr].COMP;                                         \
            u64 aa = pk2(av, av);                                           \
            fma2(acc[rr][0], aa, bv.x); fma2(acc[rr][1], aa, bv.y);         \
        }                                                                   \
        kk++;                                                               \
    }

__device__ void conv_block(float *dsm, int t, int o0,
    const float * __restrict__ Ws, const float * __restrict__ bs,
    const float * __restrict__ Wrs, const float * __restrict__ brs,
    const float * __restrict__ bc, float * __restrict__ out)
{
    float (*dis_s)[CK] = (float (*)[CK])dsm;                    // [128][10]
    float (*As)[36] = (float (*)[36])(dsm + 1280);              // [128][36]
    float (*Bs)[128] = (float (*)[128])(dsm + 1280 + 128 * 36); // [32][128]
    float *wmb = dsm + 1280 + 128 * 36 + 32 * 128;              // [128][32]
    float *s1b = wmb + 128 * 32;                                // [128][64]
    int tid = threadIdx.x;
    int tx = tid & 31, ty = tid >> 5;
    int fb = tid >> 2, fq = tid & 3;        // fold mapping: b, 16-hs group
    if (tid < BB) calc_dis(t, tid, dis_s[tid]);
    for (int e = tid; e < 128 * 64; e += 512) s1b[e] = 0.f;
    __syncthreads();

    u64 acc[8][2];
    #pragma unroll
    for (int a = 0; a < 8; a++) { acc[a][0] = 0ull; acc[a][1] = 0ull; }

    const int NCH = (HH / 32) * CK;   // 120, ch = ic*10 + k
    float4 pa[2], pb[2], wa[2];
    {
        int s = t - (CK - 1);
        #pragma unroll
        for (int l = 0; l < 2; l++) {
            int f = tid + l * 512;
            int ab = f >> 3, ai = (f & 7) * 4;
            pa[l].x = pa[l].y = pa[l].z = pa[l].w = 0.f;
            if (s >= 0) pa[l] = *(const float4 *)&g_h[((size_t)s * BB + ab) * HH + ai];
            int br_ = f >> 5, bo = (f & 31) * 4;
            pb[l] = *(const float4 *)&g_wct[(size_t)br_ * HH + o0 + bo];
        }
    }
    for (int ch = 0; ch < NCH; ch++) {
        int k = ch % 10, ic = ch / 10;
        __syncthreads();
        #pragma unroll
        for (int l = 0; l < 2; l++) {
            int f = tid + l * 512;
            int ab = f >> 3, ai = (f & 7) * 4;
            float d = dis_s[ab][k];
            float4 v = pa[l];
            v.x *= d; v.y *= d; v.z *= d; v.w *= d;
            *(float4 *)&As[ab][ai] = v;
            if (k == 0) wa[l] = v;
            else { wa[l].x += v.x; wa[l].y += v.y; wa[l].z += v.z; wa[l].w += v.w; }
            if (k == 9) {
                float4 w;
                w.x = wa[l].x * .1f; w.y = wa[l].y * .1f;
                w.z = wa[l].z * .1f; w.w = wa[l].w * .1f;
                *(float4 *)&wmb[ab * 32 + ((f & 7) * 4)] = w;
            }
            int br_ = f >> 5, bo = (f & 31) * 4;
            *(float4 *)&Bs[br_][bo] = pb[l];
        }
        __syncthreads();
        if (ch + 1 < NCH) {
            int k2 = (ch + 1) % 10, i0 = ((ch + 1) / 10) * 32, s = t - (CK - 1) + k2;
            #pragma unroll
            for (int l = 0; l < 2; l++) {
                int f = tid + l * 512;
                int ab = f >> 3, ai = (f & 7) * 4;
                pa[l].x = pa[l].y = pa[l].z = pa[l].w = 0.f;
                if (s >= 0) pa[l] = *(const float4 *)&g_h[((size_t)s * BB + ab) * HH + i0 + ai];
                int br_ = f >> 5, bo = (f & 31) * 4;
                pb[l] = *(const float4 *)&g_wct[((size_t)k2 * HH + i0 + br_) * HH + o0 + bo];
            }
        }
        #pragma unroll
        for (int kq = 0; kq < 8; kq++) {
            float4 a4[8];
            #pragma unroll
            for (int rr = 0; rr < 8; rr++)
                a4[rr] = *(const float4 *)&As[ty * 8 + rr][kq * 4];
            int kk = kq * 4;
            CONV_FFMA(x) CONV_FFMA(y) CONV_FFMA(z) CONV_FFMA(w)
        }
        if (k == 9) {      // fold wm chunk into s1 (i0 = ic*32)
            int i0 = ic * 32;
            u64 fa[8];
            #pragma unroll
            for (int a = 0; a < 8; a++) fa[a] = 0ull;
            #pragma unroll 4
            for (int j = 0; j < 32; j++) {
                float w = wmb[fb * 32 + j];
                u64 ww = pk2(w, w);
                const ulonglong2 *wp = (const ulonglong2 *)&Ws[(i0 + j) * HSS + fq * 16];
                ulonglong2 w0 = wp[0], w1 = wp[1], w2 = wp[2], w3 = wp[3];
                fma2(fa[0], ww, w0.x); fma2(fa[1], ww, w0.y);
                fma2(fa[2], ww, w1.x); fma2(fa[3], ww, w1.y);
                fma2(fa[4], ww, w2.x); fma2(fa[5], ww, w2.y);
                fma2(fa[6], ww, w3.x); fma2(fa[7], ww, w3.y);
            }
            float *sp = &s1b[fb * 64 + fq * 16];
            #pragma unroll
            for (int a = 0; a < 8; a++) {
                float2 v = up2(fa[a]);
                sp[a * 2] += v.x; sp[a * 2 + 1] += v.y;
            }
        }
    }
    // s1 = relu(s1 + bs)
    {
        float *sp = &s1b[fb * 64 + fq * 16];
        #pragma unroll
        for (int a = 0; a < 16; a++)
            sp[a] = fmaxf(sp[a] + bs[fq * 16 + a], 0.f);
    }
    __syncthreads();
    // theme for own (b, o-quad) + final epilogue
    float4 bc4 = *(const float4 *)&bc[o0 + tx * 4];
    #pragma unroll
    for (int rr = 0; rr < 8; rr++) {
        int b = ty * 8 + rr;
        u64 ta0 = 0ull, ta1 = 0ull;
        #pragma unroll 8
        for (int hs = 0; hs < HSS; hs++) {
            float sv = s1b[b * 64 + hs];
            u64 ss = pk2(sv, sv);
            ulonglong2 wr = *(const ulonglong2 *)&Wrs[hs * HH + o0 + tx * 4];
            fma2(ta0, ss, wr.x); fma2(ta1, ss, wr.y);
        }
        float4 br4 = *(const float4 *)&brs[o0 + tx * 4];
        float2 t0 = up2(ta0), t1 = up2(ta1);
        float4 th;
        th.x = sgm(t0.x + br4.x); th.y = sgm(t0.y + br4.y);
        th.z = sgm(t1.x + br4.z); th.w = sgm(t1.y + br4.w);
        float2 v0 = up2(acc[rr][0]), v1 = up2(acc[rr][1]);
        float4 hh = *(const float4 *)&g_h[((size_t)t * BB + b) * HH + o0 + tx * 4];
        float4 w;
        w.x = th.x * (v0.x + bc4.x) + hh.x;
        w.y = th.y * (v0.y + bc4.y) + hh.y;
        w.z = th.z * (v1.x + bc4.z) + hh.z;
        w.w = th.w * (v1.y + bc4.w) + hh.w;
        *(float4 *)&out[((size_t)b * TT + t) * HH + o0 + tx * 4] = w;
    }
}

// ---------- mega: phase1 (blocks 0..95) + overlapped conv workers ----------
__global__ __launch_bounds__(512, 1) void mega_kernel(
    const float * __restrict__ Wr,
    const float * __restrict__ Ws, const float * __restrict__ bs,
    const float * __restrict__ Wrs, const float * __restrict__ brs,
    const float * __restrict__ bc, float * __restrict__ out)
{
    extern __shared__ float dsm[];
    __shared__ unsigned s_task;

    if (blockIdx.x < NBLK) phase1_body(Wr, dsm, blockIdx.x);
    __syncthreads();

    const unsigned NTASK = TT * 3;
    for (;;) {
        if (threadIdx.x == 0) s_task = atomicAdd(&g_task, 1u);
        __syncthreads();
        unsigned task = s_task;
        if (task >= NTASK) break;
        int t = task / 3, r = task % 3;
        if (threadIdx.x == 0) wait_gen_ge(t);
        __syncthreads();
        conv_block(dsm, t, r * 128, Ws, bs, Wrs, brs, bc, out);
        __syncthreads();
    }
}

extern "C" void kernel_launch(void* const* d_in, const int* in_sizes, int n_in,
                              void* d_out, int out_size) {
    const float *x   = (const float *)d_in[0];
    const float *Wk  = (const float *)d_in[2];
    const float *bk  = (const float *)d_in[3];
    const float *Wr  = (const float *)d_in[4];
    const float *br  = (const float *)d_in[5];
    const float *Ws  = (const float *)d_in[6];
    const float *bs  = (const float *)d_in[7];
    const float *Wrs = (const float *)d_in[8];
    const float *brs = (const float *)d_in[9];
    const float *Wc  = (const float *)d_in[10];
    const float *bc  = (const float *)d_in[11];
    float *out = (float *)d_out;

    const int mg_smem = (KH * 64 + KH * 8 + KH * APAD + 4 * 192 + 96 + 96) * 4; // 175872
    cudaFuncSetAttribute(mega_kernel, cudaFuncAttributeMaxDynamicSharedMemorySize, mg_smem);

    init_kernel<<<1, 256>>>();
    wct_kernel<<<(CK * HH * HH + 255) / 256, 256>>>(Wc);
    xk_kernel<<<dim3(512, 13), 256>>>(x, Wk, bk, Wr, br);
    mega_kernel<<<148, 512, mg_smem>>>(Wr, Ws, bs, Wrs, brs, bc, out);
}